// round 2
// baseline (speedup 1.0000x reference)
#include <cuda_runtime.h>
#include <math.h>

#define D       64
#define NMAX    100000
#define EMAX    2000000

// Scratch (no allocations allowed -> __device__ globals)
__device__ float g_xl[NMAX * D];       // transformed features xl = x@W + b
__device__ int   g_rowptr[NMAX + 1];   // CSR row pointers (by destination)
__device__ int   g_cursor[NMAX];       // degree counts / scatter cursors
__device__ int   g_colv[EMAX];         // CSR column (source) indices

// ---------------------------------------------------------------------------
// K0: zero the per-node counters (must happen every replay: graph-safe reset)
__global__ void k_init(int n) {
    int i = blockIdx.x * blockDim.x + threadIdx.x;
    if (i < n) g_cursor[i] = 0;
}

// ---------------------------------------------------------------------------
// K1: xl = x @ W + b.   256 threads/block, 32 rows/block, 8 cols/thread.
__global__ void k_gemm(const float* __restrict__ x,
                       const float* __restrict__ W,
                       const float* __restrict__ b, int n) {
    __shared__ float Ws[D * D];
    __shared__ float xs[32 * D];
    int tid = threadIdx.x;

    // Load W (64x64 = 16KB) into smem
    for (int i = tid; i < D * D / 4; i += 256)
        ((float4*)Ws)[i] = ((const float4*)W)[i];

    // Load 32-row x tile
    int r0 = blockIdx.x * 32;
    for (int i = tid; i < 32 * D / 4; i += 256) {
        int row = r0 + i / (D / 4);
        ((float4*)xs)[i] = (row < n) ? ((const float4*)x)[row * (D / 4) + i % (D / 4)]
                                     : make_float4(0.f, 0.f, 0.f, 0.f);
    }
    __syncthreads();

    int rl = tid >> 3;        // local row 0..31
    int c0 = (tid & 7) * 8;   // column group base
    float acc[8];
#pragma unroll
    for (int j = 0; j < 8; j++) acc[j] = b[c0 + j];

#pragma unroll 4
    for (int k = 0; k < D; k++) {
        float xv = xs[rl * D + k];
        const float* wr = &Ws[k * D + c0];
#pragma unroll
        for (int j = 0; j < 8; j++) acc[j] = fmaf(xv, wr[j], acc[j]);
    }

    int row = r0 + rl;
    if (row < n) {
#pragma unroll
        for (int j = 0; j < 8; j++) g_xl[row * D + c0 + j] = acc[j];
    }
}

// ---------------------------------------------------------------------------
// K2: per-destination degree counts  (edge_index is int32 in the harness)
__global__ void k_count(const int* __restrict__ ei, int E) {
    int e = blockIdx.x * blockDim.x + threadIdx.x;
    if (e < E) atomicAdd(&g_cursor[ei[e]], 1);
}

// ---------------------------------------------------------------------------
// K3: single-block exclusive scan of degrees -> rowptr; reset cursors to start
__global__ void k_scan(int n) {
    __shared__ int sh[1024];
    int tid = threadIdx.x;
    int chunk = (n + 1023) / 1024;
    int base = tid * chunk;

    int lsum = 0;
    for (int i = 0; i < chunk; i++) {
        int idx = base + i;
        if (idx < n) lsum += g_cursor[idx];
    }
    sh[tid] = lsum;
    __syncthreads();

    // Hillis–Steele inclusive scan over 1024 partials
    for (int off = 1; off < 1024; off <<= 1) {
        int v = (tid >= off) ? sh[tid - off] : 0;
        __syncthreads();
        sh[tid] += v;
        __syncthreads();
    }

    int run = sh[tid] - lsum;  // exclusive prefix for this chunk
    for (int i = 0; i < chunk; i++) {
        int idx = base + i;
        if (idx < n) {
            int d = g_cursor[idx];
            g_rowptr[idx] = run;
            g_cursor[idx] = run;  // scatter cursor starts at segment base
            run += d;
        }
    }
    if (tid == 1023) g_rowptr[n] = sh[1023];
}

// ---------------------------------------------------------------------------
// K4: scatter source indices into CSR order (order within a segment is
// irrelevant: softmax + sum are permutation-invariant)
__global__ void k_scatter(const int* __restrict__ ei, int E) {
    int e = blockIdx.x * blockDim.x + threadIdx.x;
    if (e < E) {
        int r = ei[e];
        int c = ei[E + e];
        int pos = atomicAdd(&g_cursor[r], 1);
        g_colv[pos] = c;
    }
}

// ---------------------------------------------------------------------------
// K5: one warp per destination node. Single pass over incident edges with
// online softmax: dot -> leaky_relu -> running (max, sum, weighted acc).
__global__ void k_attn(float* __restrict__ out, int n) {
    int w = (blockIdx.x * blockDim.x + threadIdx.x) >> 5;
    int lane = threadIdx.x & 31;
    if (w >= n) return;

    const float2* xlv = (const float2*)g_xl;
    float2 xi = xlv[w * 32 + lane];  // 64 floats of xl[w] across the warp

    int p0 = g_rowptr[w];
    int p1 = g_rowptr[w + 1];

    float m = -INFINITY;   // running max (uniform across warp)
    float ss = 0.f;        // running exp-sum
    float a0 = 0.f, a1 = 0.f;  // weighted feature accumulator (2 floats/lane)

    for (int p = p0; p < p1; p++) {
        int c = g_colv[p];
        float2 xj = xlv[c * 32 + lane];

        float d = xi.x * xj.x + xi.y * xj.y;
#pragma unroll
        for (int o = 16; o >= 1; o >>= 1)
            d += __shfl_xor_sync(0xffffffffu, d, o);

        float a = d > 0.f ? d : 0.2f * d;  // leaky_relu(0.2)

        if (a > m) {  // uniform branch (a, m identical across lanes)
            float sc = __expf(m - a);  // exp(-inf) = 0 on first edge
            ss *= sc; a0 *= sc; a1 *= sc;
            m = a;
        }
        float e = __expf(a - m);
        ss += e;
        a0 = fmaf(e, xj.x, a0);
        a1 = fmaf(e, xj.y, a1);
    }

    float inv = 1.0f / (ss + 1e-16f);
    ((float2*)out)[w * 32 + lane] = make_float2(a0 * inv, a1 * inv);
}

// ---------------------------------------------------------------------------
extern "C" void kernel_launch(void* const* d_in, const int* in_sizes, int n_in,
                              void* d_out, int out_size) {
    const float* x  = (const float*)d_in[0];
    const int*   ei = (const int*)d_in[1];   // edge_index downcast to int32 by harness
    const float* W  = (const float*)d_in[2];
    const float* b  = (const float*)d_in[3];

    int n = in_sizes[0] / D;
    int E = in_sizes[1] / 2;

    k_init<<<(n + 255) / 256, 256>>>(n);
    k_gemm<<<(n + 31) / 32, 256>>>(x, W, b, n);
    k_count<<<(E + 255) / 256, 256>>>(ei, E);
    k_scan<<<1, 1024>>>(n);
    k_scatter<<<(E + 255) / 256, 256>>>(ei, E);
    k_attn<<<(n + 7) / 8, 256>>>((float*)d_out, n);
}

// round 3
// speedup vs baseline: 1.6085x; 1.6085x over previous
#include <cuda_runtime.h>
#include <math.h>

#define D       64
#define NMAX    100000
#define EMAX    2000000
#define SCAN_NB 128   // max blocks in level-1 scan (ceil(100000/1024)=98)

// Scratch (no allocations allowed -> __device__ globals)
__device__ float g_xl[NMAX * D];       // transformed features xl = x@W + b
__device__ int   g_rowptr[NMAX + 1];   // CSR row pointers (by destination)
__device__ int   g_cursor[NMAX];       // degree counts / scatter cursors
__device__ int   g_colv[EMAX];         // CSR column (source) indices
__device__ int   g_blocksums[SCAN_NB]; // level-1 scan block totals

// ---------------------------------------------------------------------------
// K0: zero the per-node counters (must happen every replay: graph-safe reset)
__global__ void k_init(int n) {
    int i = blockIdx.x * blockDim.x + threadIdx.x;
    if (i < n) g_cursor[i] = 0;
}

// ---------------------------------------------------------------------------
// K1: xl = x @ W + b.   256 threads/block, 32 rows/block, 8 cols/thread.
__global__ void k_gemm(const float* __restrict__ x,
                       const float* __restrict__ W,
                       const float* __restrict__ b, int n) {
    __shared__ float Ws[D * D];
    __shared__ float xs[32 * D];
    int tid = threadIdx.x;

    for (int i = tid; i < D * D / 4; i += 256)
        ((float4*)Ws)[i] = ((const float4*)W)[i];

    int r0 = blockIdx.x * 32;
    for (int i = tid; i < 32 * D / 4; i += 256) {
        int row = r0 + i / (D / 4);
        ((float4*)xs)[i] = (row < n) ? ((const float4*)x)[row * (D / 4) + i % (D / 4)]
                                     : make_float4(0.f, 0.f, 0.f, 0.f);
    }
    __syncthreads();

    int rl = tid >> 3;
    int c0 = (tid & 7) * 8;
    float acc[8];
#pragma unroll
    for (int j = 0; j < 8; j++) acc[j] = b[c0 + j];

#pragma unroll 4
    for (int k = 0; k < D; k++) {
        float xv = xs[rl * D + k];
        const float* wr = &Ws[k * D + c0];
#pragma unroll
        for (int j = 0; j < 8; j++) acc[j] = fmaf(xv, wr[j], acc[j]);
    }

    int row = r0 + rl;
    if (row < n) {
#pragma unroll
        for (int j = 0; j < 8; j++) g_xl[row * D + c0 + j] = acc[j];
    }
}

// ---------------------------------------------------------------------------
// K2: per-destination degree counts  (edge_index is int32 in the harness)
__global__ void k_count(const int* __restrict__ ei, int E) {
    int e = blockIdx.x * blockDim.x + threadIdx.x;
    if (e < E) atomicAdd(&g_cursor[ei[e]], 1);
}

// ---------------------------------------------------------------------------
// K3a: level-1 scan — each 1024-thread block scans its tile of degrees.
// Writes block-local exclusive prefix into g_rowptr and block total.
__global__ void k_scan1(int n) {
    __shared__ int wsum[32];
    int i = blockIdx.x * 1024 + threadIdx.x;
    int lane = threadIdx.x & 31, wid = threadIdx.x >> 5;
    int v = (i < n) ? g_cursor[i] : 0;
    int s = v;
#pragma unroll
    for (int o = 1; o < 32; o <<= 1) {
        int t = __shfl_up_sync(0xffffffffu, s, o);
        if (lane >= o) s += t;
    }
    if (lane == 31) wsum[wid] = s;
    __syncthreads();
    if (wid == 0) {
        int ws = wsum[lane];
#pragma unroll
        for (int o = 1; o < 32; o <<= 1) {
            int t = __shfl_up_sync(0xffffffffu, ws, o);
            if (lane >= o) ws += t;
        }
        wsum[lane] = ws;   // inclusive warp totals
    }
    __syncthreads();
    int base = (wid > 0) ? wsum[wid - 1] : 0;
    if (i < n) g_rowptr[i] = base + s - v;            // block-local exclusive
    if (threadIdx.x == 1023) g_blocksums[blockIdx.x] = base + s;  // block total
}

// K3b: tiny scan of block totals -> exclusive block offsets
__global__ void k_scan2(int nb) {
    __shared__ int sh[SCAN_NB];
    int t = threadIdx.x;
    int v = (t < nb) ? g_blocksums[t] : 0;
    sh[t] = v;
    __syncthreads();
    for (int o = 1; o < SCAN_NB; o <<= 1) {
        int u = (t >= o) ? sh[t - o] : 0;
        __syncthreads();
        sh[t] += u;
        __syncthreads();
    }
    if (t < nb) g_blocksums[t] = sh[t] - v;  // exclusive
}

// K3c: add block offsets; init scatter cursors; finalize rowptr[n]
__global__ void k_scan3(int n, int E) {
    int i = blockIdx.x * 1024 + threadIdx.x;
    if (i < n) {
        int v = g_rowptr[i] + g_blocksums[blockIdx.x];
        g_rowptr[i] = v;
        g_cursor[i] = v;
    }
    if (i == 0) g_rowptr[n] = E;
}

// ---------------------------------------------------------------------------
// K4: scatter source indices into CSR order (order within a segment is
// irrelevant: softmax + sum are permutation-invariant)
__global__ void k_scatter(const int* __restrict__ ei, int E) {
    int e = blockIdx.x * blockDim.x + threadIdx.x;
    if (e < E) {
        int r = ei[e];
        int c = ei[E + e];
        int pos = atomicAdd(&g_cursor[r], 1);
        g_colv[pos] = c;
    }
}

// ---------------------------------------------------------------------------
// K5: one warp per destination node, TWO edges per iteration (half-warp per
// edge, float4 per lane). Online softmax: per pair compute new max once,
// rescale, then both exps against the final max (mathematically exact).
__global__ void k_attn(float* __restrict__ out, int n) {
    int w = (blockIdx.x * blockDim.x + threadIdx.x) >> 5;
    int lane = threadIdx.x & 31;
    if (w >= n) return;
    int half = lane >> 4;   // which edge of the pair this lane serves
    int hl = lane & 15;     // 16 lanes x float4 = 64 floats per row

    const float4* xlv = (const float4*)g_xl;
    float4 xi = xlv[w * 16 + hl];

    int p0 = g_rowptr[w], p1 = g_rowptr[w + 1];

    float m = -INFINITY, ss = 0.f;
    float4 acc = make_float4(0.f, 0.f, 0.f, 0.f);

    for (int p = p0; p < p1; p += 2) {
        int pm = p + half;
        bool valid = pm < p1;            // uniform within each half
        int c = valid ? g_colv[pm] : 0;
        float4 xj = xlv[c * 16 + hl];

        float d = xi.x * xj.x + xi.y * xj.y + xi.z * xj.z + xi.w * xj.w;
#pragma unroll
        for (int o = 8; o >= 1; o >>= 1)
            d += __shfl_xor_sync(0xffffffffu, d, o);   // stays within half

        float a = d > 0.f ? d : 0.2f * d;  // leaky_relu(0.2)
        if (!valid) a = -INFINITY;

        float aA = __shfl_sync(0xffffffffu, a, 0);
        float aB = __shfl_sync(0xffffffffu, a, 16);

        float mn = fmaxf(m, fmaxf(aA, aB));
        if (mn > m) {   // uniform branch
            float sc = __expf(m - mn);
            ss *= sc;
            acc.x *= sc; acc.y *= sc; acc.z *= sc; acc.w *= sc;
            m = mn;
        }
        float eA = __expf(aA - m);
        float eB = __expf(aB - m);   // exp(-inf) = 0 for invalid tail
        ss += eA + eB;
        float e = half ? eB : eA;
        acc.x = fmaf(e, xj.x, acc.x);
        acc.y = fmaf(e, xj.y, acc.y);
        acc.z = fmaf(e, xj.z, acc.z);
        acc.w = fmaf(e, xj.w, acc.w);
    }

    // combine the two halves' accumulators
    acc.x += __shfl_xor_sync(0xffffffffu, acc.x, 16);
    acc.y += __shfl_xor_sync(0xffffffffu, acc.y, 16);
    acc.z += __shfl_xor_sync(0xffffffffu, acc.z, 16);
    acc.w += __shfl_xor_sync(0xffffffffu, acc.w, 16);

    float inv = 1.0f / (ss + 1e-16f);
    if (half == 0)
        ((float4*)out)[w * 16 + hl] =
            make_float4(acc.x * inv, acc.y * inv, acc.z * inv, acc.w * inv);
}

// ---------------------------------------------------------------------------
extern "C" void kernel_launch(void* const* d_in, const int* in_sizes, int n_in,
                              void* d_out, int out_size) {
    const float* x  = (const float*)d_in[0];
    const int*   ei = (const int*)d_in[1];   // edge_index downcast to int32
    const float* W  = (const float*)d_in[2];
    const float* b  = (const float*)d_in[3];

    int n = in_sizes[0] / D;
    int E = in_sizes[1] / 2;
    int nb = (n + 1023) / 1024;

    k_init<<<(n + 255) / 256, 256>>>(n);
    k_gemm<<<(n + 31) / 32, 256>>>(x, W, b, n);
    k_count<<<(E + 255) / 256, 256>>>(ei, E);
    k_scan1<<<nb, 1024>>>(n);
    k_scan2<<<1, SCAN_NB>>>(nb);
    k_scan3<<<nb, 1024>>>(n, E);
    k_scatter<<<(E + 255) / 256, 256>>>(ei, E);
    k_attn<<<(n + 7) / 8, 256>>>((float*)d_out, n);
}

// round 4
// speedup vs baseline: 1.6598x; 1.0319x over previous
#include <cuda_runtime.h>
#include <math.h>

#define D       64
#define NMAX    100000
#define EMAX    2000000
#define SCAN_NB 128   // max blocks in level-1 scan (ceil(100000/1024)=98)

// Scratch (no allocations allowed -> __device__ globals)
__device__ float g_xl[NMAX * D];       // transformed features xl = x@W + b
__device__ int   g_rowptr[NMAX + 1];   // CSR row pointers (by destination)
__device__ int   g_cursor[NMAX];       // degree counts / scatter cursors
__device__ int   g_colv[EMAX];         // CSR column (source) indices
__device__ int   g_blocksums[SCAN_NB]; // level-1 scan block totals

// ---------------------------------------------------------------------------
// K0: zero the per-node counters (must happen every replay: graph-safe reset)
__global__ void k_init(int n) {
    int i = blockIdx.x * blockDim.x + threadIdx.x;
    if (i < n) g_cursor[i] = 0;
}

// ---------------------------------------------------------------------------
// K1: xl = x @ W + b.   256 threads/block, 32 rows/block, 8 cols/thread.
__global__ void k_gemm(const float* __restrict__ x,
                       const float* __restrict__ W,
                       const float* __restrict__ b, int n) {
    __shared__ float Ws[D * D];
    __shared__ float xs[32 * D];
    int tid = threadIdx.x;

    for (int i = tid; i < D * D / 4; i += 256)
        ((float4*)Ws)[i] = ((const float4*)W)[i];

    int r0 = blockIdx.x * 32;
    for (int i = tid; i < 32 * D / 4; i += 256) {
        int row = r0 + i / (D / 4);
        ((float4*)xs)[i] = (row < n) ? ((const float4*)x)[row * (D / 4) + i % (D / 4)]
                                     : make_float4(0.f, 0.f, 0.f, 0.f);
    }
    __syncthreads();

    int rl = tid >> 3;
    int c0 = (tid & 7) * 8;
    float acc[8];
#pragma unroll
    for (int j = 0; j < 8; j++) acc[j] = b[c0 + j];

#pragma unroll 4
    for (int k = 0; k < D; k++) {
        float xv = xs[rl * D + k];
        const float* wr = &Ws[k * D + c0];
#pragma unroll
        for (int j = 0; j < 8; j++) acc[j] = fmaf(xv, wr[j], acc[j]);
    }

    int row = r0 + rl;
    if (row < n) {
#pragma unroll
        for (int j = 0; j < 8; j++) g_xl[row * D + c0 + j] = acc[j];
    }
}

// ---------------------------------------------------------------------------
// K2: per-destination degree counts  (edge_index is int32 in the harness)
__global__ void k_count(const int* __restrict__ ei, int E) {
    int e = blockIdx.x * blockDim.x + threadIdx.x;
    if (e < E) atomicAdd(&g_cursor[ei[e]], 1);
}

// ---------------------------------------------------------------------------
// K3a: level-1 scan — each 1024-thread block scans its tile of degrees.
__global__ void k_scan1(int n) {
    __shared__ int wsum[32];
    int i = blockIdx.x * 1024 + threadIdx.x;
    int lane = threadIdx.x & 31, wid = threadIdx.x >> 5;
    int v = (i < n) ? g_cursor[i] : 0;
    int s = v;
#pragma unroll
    for (int o = 1; o < 32; o <<= 1) {
        int t = __shfl_up_sync(0xffffffffu, s, o);
        if (lane >= o) s += t;
    }
    if (lane == 31) wsum[wid] = s;
    __syncthreads();
    if (wid == 0) {
        int ws = wsum[lane];
#pragma unroll
        for (int o = 1; o < 32; o <<= 1) {
            int t = __shfl_up_sync(0xffffffffu, ws, o);
            if (lane >= o) ws += t;
        }
        wsum[lane] = ws;
    }
    __syncthreads();
    int base = (wid > 0) ? wsum[wid - 1] : 0;
    if (i < n) g_rowptr[i] = base + s - v;
    if (threadIdx.x == 1023) g_blocksums[blockIdx.x] = base + s;
}

// K3b: tiny scan of block totals -> exclusive block offsets
__global__ void k_scan2(int nb) {
    __shared__ int sh[SCAN_NB];
    int t = threadIdx.x;
    int v = (t < nb) ? g_blocksums[t] : 0;
    sh[t] = v;
    __syncthreads();
    for (int o = 1; o < SCAN_NB; o <<= 1) {
        int u = (t >= o) ? sh[t - o] : 0;
        __syncthreads();
        sh[t] += u;
        __syncthreads();
    }
    if (t < nb) g_blocksums[t] = sh[t] - v;
}

// K3c: add block offsets; init scatter cursors; finalize rowptr[n]
__global__ void k_scan3(int n, int E) {
    int i = blockIdx.x * 1024 + threadIdx.x;
    if (i < n) {
        int v = g_rowptr[i] + g_blocksums[blockIdx.x];
        g_rowptr[i] = v;
        g_cursor[i] = v;
    }
    if (i == 0) g_rowptr[n] = E;
}

// ---------------------------------------------------------------------------
// K4: scatter source indices into CSR order
__global__ void k_scatter(const int* __restrict__ ei, int E) {
    int e = blockIdx.x * blockDim.x + threadIdx.x;
    if (e < E) {
        int r = ei[e];
        int c = ei[E + e];
        int pos = atomicAdd(&g_cursor[r], 1);
        g_colv[pos] = c;
    }
}

// ---------------------------------------------------------------------------
// K5: one warp per destination node, FOUR edges per iteration (8 lanes per
// edge, 2xfloat4 per lane = 64 floats/row). Online softmax, exact.
__global__ void k_attn(float* __restrict__ out, int n) {
    int w = (blockIdx.x * blockDim.x + threadIdx.x) >> 5;
    int lane = threadIdx.x & 31;
    if (w >= n) return;
    int quarter = lane >> 3;   // which of the 4 edges this octet serves
    int ql = lane & 7;         // 8 lanes x 2 float4 = 64 floats per row

    const float4* xlv = (const float4*)g_xl;
    float4 xi0 = xlv[w * 16 + ql * 2];
    float4 xi1 = xlv[w * 16 + ql * 2 + 1];

    int p0 = g_rowptr[w], p1 = g_rowptr[w + 1];

    float m = -INFINITY, ss = 0.f;
    float4 ac0 = make_float4(0.f, 0.f, 0.f, 0.f);
    float4 ac1 = make_float4(0.f, 0.f, 0.f, 0.f);

    for (int p = p0; p < p1; p += 4) {
        int pm = p + quarter;
        bool valid = pm < p1;             // uniform within each octet
        int c = valid ? g_colv[pm] : 0;
        float4 xj0 = xlv[c * 16 + ql * 2];
        float4 xj1 = xlv[c * 16 + ql * 2 + 1];

        float d = xi0.x * xj0.x + xi0.y * xj0.y + xi0.z * xj0.z + xi0.w * xj0.w
                + xi1.x * xj1.x + xi1.y * xj1.y + xi1.z * xj1.z + xi1.w * xj1.w;
#pragma unroll
        for (int o = 4; o >= 1; o >>= 1)
            d += __shfl_xor_sync(0xffffffffu, d, o);   // stays within octet

        float a = d > 0.f ? d : 0.2f * d;  // leaky_relu(0.2)
        if (!valid) a = -INFINITY;

        float a0 = __shfl_sync(0xffffffffu, a, 0);
        float a1 = __shfl_sync(0xffffffffu, a, 8);
        float a2 = __shfl_sync(0xffffffffu, a, 16);
        float a3 = __shfl_sync(0xffffffffu, a, 24);

        float mn = fmaxf(fmaxf(m, fmaxf(a0, a1)), fmaxf(a2, a3));
        if (mn > m) {   // uniform branch across the warp
            float sc = __expf(m - mn);   // exp(-inf)=0 on first iteration
            ss *= sc;
            ac0.x *= sc; ac0.y *= sc; ac0.z *= sc; ac0.w *= sc;
            ac1.x *= sc; ac1.y *= sc; ac1.z *= sc; ac1.w *= sc;
            m = mn;
        }
        // exp-sum over the 4 distinct alphas (replicated in every lane)
        ss += __expf(a0 - m) + __expf(a1 - m) + __expf(a2 - m) + __expf(a3 - m);
        // each octet accumulates its own edge with its own weight
        float e = __expf(a - m);          // 0 for invalid tail (a = -inf)
        ac0.x = fmaf(e, xj0.x, ac0.x);
        ac0.y = fmaf(e, xj0.y, ac0.y);
        ac0.z = fmaf(e, xj0.z, ac0.z);
        ac0.w = fmaf(e, xj0.w, ac0.w);
        ac1.x = fmaf(e, xj1.x, ac1.x);
        ac1.y = fmaf(e, xj1.y, ac1.y);
        ac1.z = fmaf(e, xj1.z, ac1.z);
        ac1.w = fmaf(e, xj1.w, ac1.w);
    }

    // combine the 4 octets' accumulators (offsets 8 and 16)
#pragma unroll
    for (int o = 8; o <= 16; o <<= 1) {
        ac0.x += __shfl_xor_sync(0xffffffffu, ac0.x, o);
        ac0.y += __shfl_xor_sync(0xffffffffu, ac0.y, o);
        ac0.z += __shfl_xor_sync(0xffffffffu, ac0.z, o);
        ac0.w += __shfl_xor_sync(0xffffffffu, ac0.w, o);
        ac1.x += __shfl_xor_sync(0xffffffffu, ac1.x, o);
        ac1.y += __shfl_xor_sync(0xffffffffu, ac1.y, o);
        ac1.z += __shfl_xor_sync(0xffffffffu, ac1.z, o);
        ac1.w += __shfl_xor_sync(0xffffffffu, ac1.w, o);
    }

    float inv = 1.0f / (ss + 1e-16f);
    if (quarter == 0) {
        ((float4*)out)[w * 16 + ql * 2] =
            make_float4(ac0.x * inv, ac0.y * inv, ac0.z * inv, ac0.w * inv);
        ((float4*)out)[w * 16 + ql * 2 + 1] =
            make_float4(ac1.x * inv, ac1.y * inv, ac1.z * inv, ac1.w * inv);
    }
}

// ---------------------------------------------------------------------------
extern "C" void kernel_launch(void* const* d_in, const int* in_sizes, int n_in,
                              void* d_out, int out_size) {
    const float* x  = (const float*)d_in[0];
    const int*   ei = (const int*)d_in[1];   // edge_index downcast to int32
    const float* W  = (const float*)d_in[2];
    const float* b  = (const float*)d_in[3];

    int n = in_sizes[0] / D;
    int E = in_sizes[1] / 2;
    int nb = (n + 1023) / 1024;

    k_init<<<(n + 255) / 256, 256>>>(n);
    k_gemm<<<(n + 31) / 32, 256>>>(x, W, b, n);
    k_count<<<(E + 255) / 256, 256>>>(ei, E);
    k_scan1<<<nb, 1024>>>(n);
    k_scan2<<<1, SCAN_NB>>>(nb);
    k_scan3<<<nb, 1024>>>(n, E);
    k_scatter<<<(E + 255) / 256, 256>>>(ei, E);
    k_attn<<<(n + 7) / 8, 256>>>((float*)d_out, n);
}

// round 5
// speedup vs baseline: 2.5161x; 1.5159x over previous
#include <cuda_runtime.h>
#include <math.h>

#define D       64
#define NMAX    100000
#define EMAX    2000000
#define SCAN_NB 128
#define TILE_R  128   // gemm rows per block

// Scratch (no allocations allowed -> __device__ globals)
__device__ float g_xl[NMAX * D];
__device__ int   g_rowptr[NMAX + 1];
__device__ int   g_cursor[NMAX];
__device__ int   g_colv[EMAX];
__device__ int   g_blocksums[SCAN_NB];

// ---------------------------------------------------------------------------
// K0: zero per-node counters (every replay: graph-safe reset)
__global__ void k_init(int n) {
    int i = blockIdx.x * blockDim.x + threadIdx.x;
    if (i < n) g_cursor[i] = 0;
}

// ---------------------------------------------------------------------------
// K1: fused  [blocks 0..nbg)   : xl = x @ W + b  (128x64 tile, 4x8 per thread)
//            [blocks nbg..end) : per-destination degree counts
__global__ void k_gemm_count(const float* __restrict__ x,
                             const float* __restrict__ W,
                             const float* __restrict__ bias,
                             const int* __restrict__ ei,
                             int n, int E, int nbg) {
    __shared__ float Ws[D * D];           // 16KB, Ws[k*64+c]
    __shared__ float xs[D][TILE_R];       // 32KB, transposed: xs[k][row]

    if (blockIdx.x >= nbg) {
        // ---- count part ----
        int nbc = gridDim.x - nbg;
        int idx = (blockIdx.x - nbg) * 256 + threadIdx.x;
        int stride = nbc * 256;
        for (int e = idx; e < E; e += stride)
            atomicAdd(&g_cursor[ei[e]], 1);
        return;
    }

    // ---- gemm part ----
    int tid = threadIdx.x;
    int r0 = blockIdx.x * TILE_R;

    // Load W (coalesced float4)
    for (int i = tid; i < D * D / 4; i += 256)
        ((float4*)Ws)[i] = ((const float4*)W)[i];

    // Load x tile transposed: idx -> (row = idx%128, kq = idx/128)
    for (int idx = tid; idx < TILE_R * (D / 4); idx += 256) {
        int row = idx & (TILE_R - 1);
        int kq = idx >> 7;               // float4 index along k
        int grow = r0 + row;
        float4 v = (grow < n) ? ((const float4*)x)[grow * (D / 4) + kq]
                              : make_float4(0.f, 0.f, 0.f, 0.f);
        xs[kq * 4 + 0][row] = v.x;
        xs[kq * 4 + 1][row] = v.y;
        xs[kq * 4 + 2][row] = v.z;
        xs[kq * 4 + 3][row] = v.w;
    }
    __syncthreads();

    int ty = tid >> 3;        // row group 0..31 (rows ty + 32*i)
    int c0 = (tid & 7) * 8;   // 8 output columns

    float bv[8];
#pragma unroll
    for (int j = 0; j < 8; j++) bv[j] = bias[c0 + j];

    float acc[4][8];
#pragma unroll
    for (int i = 0; i < 4; i++)
#pragma unroll
        for (int j = 0; j < 8; j++) acc[i][j] = bv[j];

#pragma unroll 8
    for (int k = 0; k < D; k++) {
        float xv0 = xs[k][ty];
        float xv1 = xs[k][ty + 32];
        float xv2 = xs[k][ty + 64];
        float xv3 = xs[k][ty + 96];
        const float* wr = &Ws[k * D + c0];
#pragma unroll
        for (int j = 0; j < 8; j++) {
            float wv = wr[j];
            acc[0][j] = fmaf(xv0, wv, acc[0][j]);
            acc[1][j] = fmaf(xv1, wv, acc[1][j]);
            acc[2][j] = fmaf(xv2, wv, acc[2][j]);
            acc[3][j] = fmaf(xv3, wv, acc[3][j]);
        }
    }

#pragma unroll
    for (int i = 0; i < 4; i++) {
        int row = r0 + ty + 32 * i;
        if (row < n) {
            float4* dst = (float4*)&g_xl[row * D + c0];
            dst[0] = make_float4(acc[i][0], acc[i][1], acc[i][2], acc[i][3]);
            dst[1] = make_float4(acc[i][4], acc[i][5], acc[i][6], acc[i][7]);
        }
    }
}

// ---------------------------------------------------------------------------
// K3a: level-1 scan of degrees
__global__ void k_scan1(int n) {
    __shared__ int wsum[32];
    int i = blockIdx.x * 1024 + threadIdx.x;
    int lane = threadIdx.x & 31, wid = threadIdx.x >> 5;
    int v = (i < n) ? g_cursor[i] : 0;
    int s = v;
#pragma unroll
    for (int o = 1; o < 32; o <<= 1) {
        int t = __shfl_up_sync(0xffffffffu, s, o);
        if (lane >= o) s += t;
    }
    if (lane == 31) wsum[wid] = s;
    __syncthreads();
    if (wid == 0) {
        int ws = wsum[lane];
#pragma unroll
        for (int o = 1; o < 32; o <<= 1) {
            int t = __shfl_up_sync(0xffffffffu, ws, o);
            if (lane >= o) ws += t;
        }
        wsum[lane] = ws;
    }
    __syncthreads();
    int base = (wid > 0) ? wsum[wid - 1] : 0;
    if (i < n) g_rowptr[i] = base + s - v;
    if (threadIdx.x == 1023) g_blocksums[blockIdx.x] = base + s;
}

// K3b: scan block totals
__global__ void k_scan2(int nb) {
    __shared__ int sh[SCAN_NB];
    int t = threadIdx.x;
    int v = (t < nb) ? g_blocksums[t] : 0;
    sh[t] = v;
    __syncthreads();
    for (int o = 1; o < SCAN_NB; o <<= 1) {
        int u = (t >= o) ? sh[t - o] : 0;
        __syncthreads();
        sh[t] += u;
        __syncthreads();
    }
    if (t < nb) g_blocksums[t] = sh[t] - v;
}

// K3c: add offsets; init cursors; finalize rowptr[n]
__global__ void k_scan3(int n, int E) {
    int i = blockIdx.x * 1024 + threadIdx.x;
    if (i < n) {
        int v = g_rowptr[i] + g_blocksums[blockIdx.x];
        g_rowptr[i] = v;
        g_cursor[i] = v;
    }
    if (i == 0) g_rowptr[n] = E;
}

// ---------------------------------------------------------------------------
// K4: scatter source indices into CSR order
__global__ void k_scatter(const int* __restrict__ ei, int E) {
    int e = blockIdx.x * blockDim.x + threadIdx.x;
    if (e < E) {
        int r = ei[e];
        int c = ei[E + e];
        int pos = atomicAdd(&g_cursor[r], 1);
        g_colv[pos] = c;
    }
}

// ---------------------------------------------------------------------------
// K5: one warp per node, 4 edges/iter (octet per edge). Online softmax:
// lane-local exp-sum per octet, warp max via 2 butterflies, 1 exp per iter.
__global__ void k_attn(float* __restrict__ out, int n) {
    int w = (blockIdx.x * blockDim.x + threadIdx.x) >> 5;
    int lane = threadIdx.x & 31;
    if (w >= n) return;
    int quarter = lane >> 3;
    int ql = lane & 7;

    const float4* xlv = (const float4*)g_xl;
    float4 xi0 = xlv[w * 16 + ql * 2];
    float4 xi1 = xlv[w * 16 + ql * 2 + 1];

    int p0 = g_rowptr[w], p1 = g_rowptr[w + 1];

    float m = -INFINITY, ss = 0.f;
    float4 ac0 = make_float4(0.f, 0.f, 0.f, 0.f);
    float4 ac1 = make_float4(0.f, 0.f, 0.f, 0.f);

    int pm = p0 + quarter;
    int c = (pm < p1) ? g_colv[pm] : 0;

    for (int p = p0; p < p1; p += 4) {
        bool valid = (p + quarter) < p1;
        float4 xj0 = xlv[c * 16 + ql * 2];
        float4 xj1 = xlv[c * 16 + ql * 2 + 1];

        int pn = p + 4 + quarter;                 // prefetch next colv
        c = (pn < p1) ? g_colv[pn] : 0;

        float d = xi0.x * xj0.x + xi0.y * xj0.y + xi0.z * xj0.z + xi0.w * xj0.w
                + xi1.x * xj1.x + xi1.y * xj1.y + xi1.z * xj1.z + xi1.w * xj1.w;
        d += __shfl_xor_sync(0xffffffffu, d, 4);
        d += __shfl_xor_sync(0xffffffffu, d, 2);
        d += __shfl_xor_sync(0xffffffffu, d, 1);

        float a = d > 0.f ? d : 0.2f * d;         // leaky_relu(0.2)
        if (!valid) a = -INFINITY;

        float am = fmaxf(a, __shfl_xor_sync(0xffffffffu, a, 8));
        am = fmaxf(am, __shfl_xor_sync(0xffffffffu, am, 16));

        if (am > m) {                             // warp-uniform
            float sc = __expf(m - am);            // first iter: exp(-inf)=0
            ss *= sc;
            ac0.x *= sc; ac0.y *= sc; ac0.z *= sc; ac0.w *= sc;
            ac1.x *= sc; ac1.y *= sc; ac1.z *= sc; ac1.w *= sc;
            m = am;
        }
        float e = __expf(a - m);                  // 0 for invalid tail
        ss += e;                                  // octet-local partial sum
        ac0.x = fmaf(e, xj0.x, ac0.x);
        ac0.y = fmaf(e, xj0.y, ac0.y);
        ac0.z = fmaf(e, xj0.z, ac0.z);
        ac0.w = fmaf(e, xj0.w, ac0.w);
        ac1.x = fmaf(e, xj1.x, ac1.x);
        ac1.y = fmaf(e, xj1.y, ac1.y);
        ac1.z = fmaf(e, xj1.z, ac1.z);
        ac1.w = fmaf(e, xj1.w, ac1.w);
    }

    // combine the 4 octets (ss and accumulators)
#pragma unroll
    for (int o = 8; o <= 16; o <<= 1) {
        ss    += __shfl_xor_sync(0xffffffffu, ss, o);
        ac0.x += __shfl_xor_sync(0xffffffffu, ac0.x, o);
        ac0.y += __shfl_xor_sync(0xffffffffu, ac0.y, o);
        ac0.z += __shfl_xor_sync(0xffffffffu, ac0.z, o);
        ac0.w += __shfl_xor_sync(0xffffffffu, ac0.w, o);
        ac1.x += __shfl_xor_sync(0xffffffffu, ac1.x, o);
        ac1.y += __shfl_xor_sync(0xffffffffu, ac1.y, o);
        ac1.z += __shfl_xor_sync(0xffffffffu, ac1.z, o);
        ac1.w += __shfl_xor_sync(0xffffffffu, ac1.w, o);
    }

    float inv = 1.0f / (ss + 1e-16f);
    if (quarter == 0) {
        ((float4*)out)[w * 16 + ql * 2] =
            make_float4(ac0.x * inv, ac0.y * inv, ac0.z * inv, ac0.w * inv);
        ((float4*)out)[w * 16 + ql * 2 + 1] =
            make_float4(ac1.x * inv, ac1.y * inv, ac1.z * inv, ac1.w * inv);
    }
}

// ---------------------------------------------------------------------------
extern "C" void kernel_launch(void* const* d_in, const int* in_sizes, int n_in,
                              void* d_out, int out_size) {
    const float* x  = (const float*)d_in[0];
    const int*   ei = (const int*)d_in[1];
    const float* W  = (const float*)d_in[2];
    const float* b  = (const float*)d_in[3];

    int n = in_sizes[0] / D;
    int E = in_sizes[1] / 2;
    int nb = (n + 1023) / 1024;
    int nbg = (n + TILE_R - 1) / TILE_R;
    int nbc = (E + 1023) / 1024;            // count blocks: ~4 edges/thread

    k_init<<<(n + 255) / 256, 256>>>(n);
    k_gemm_count<<<nbg + nbc, 256>>>(x, W, b, ei, n, E, nbg);
    k_scan1<<<nb, 1024>>>(n);
    k_scan2<<<1, SCAN_NB>>>(nb);
    k_scan3<<<nb, 1024>>>(n, E);
    k_scatter<<<(E + 255) / 256, 256>>>(ei, E);
    k_attn<<<(n + 7) / 8, 256>>>((float*)d_out, n);
}